// round 8
// baseline (speedup 1.0000x reference)
#include <cuda_runtime.h>
#include <cstdint>

#define NV   2562
#define DEG  8
#define FIN  8
#define FOUT 16
#define KCH  5
#define SP   512                 // spatial = X*Y*Z
#define SP4  (SP/4)              // 128 float4 per (v,f) row-chunk
#define DD   (FIN*SP)            // 4096 floats per vertex row
#define DD4  (DD/4)              // 1024 float4

typedef unsigned long long ull;

// packed f32x2 fma: d = a*b + c (per 32-bit lane)
#define FMA2(d, a, b, c) \
    asm("fma.rn.f32x2 %0, %1, %2, %3;" : "=l"(d) : "l"(a), "l"(b), "l"(c))

#define SIGNMASK2 0x8000000080000000ULL
#define TWO2      0x4000000040000000ULL   // pack(2.0f, 2.0f)

// Scratch: 3 rolling Chebyshev levels (x1, x2, x3), 42 MB each.
__device__ float4 g_buf[3][(size_t)NV * DD4];

// One block per vertex v; 128 threads cover the 512 spatial floats as float4.
// Two f-iterations interleaved -> 16 independent gather loads in flight.
__global__ __launch_bounds__(SP4) void spmv_step_kernel(
    const float4* __restrict__ cur,  int cvs4, int cfs4,   // strides in float4 units
    const float4* __restrict__ prev, int pvs4, int pfs4,
    float4* __restrict__ next,
    const int* __restrict__ cols, const float* __restrict__ vals,
    int has_prev)
{
    __shared__ int   scol[DEG];
    __shared__ float sval[DEG];
    const int v = blockIdx.x;
    const int t = threadIdx.x;
    if (t < DEG) {
        scol[t] = cols[v * DEG + t];
        sval[t] = vals[v * DEG + t];
    }
    __syncthreads();

    #pragma unroll
    for (int f = 0; f < FIN; f += 2) {
        float4 a0 = make_float4(0.f, 0.f, 0.f, 0.f);
        float4 a1 = make_float4(0.f, 0.f, 0.f, 0.f);
        #pragma unroll
        for (int n = 0; n < DEG; ++n) {
            const size_t base = (size_t)scol[n] * cvs4 + (size_t)f * cfs4 + t;
            const float4 x0 = cur[base];
            const float4 x1 = cur[base + cfs4];
            const float  w  = sval[n];
            a0.x += w * x0.x; a0.y += w * x0.y; a0.z += w * x0.z; a0.w += w * x0.w;
            a1.x += w * x1.x; a1.y += w * x1.y; a1.z += w * x1.z; a1.w += w * x1.w;
        }
        if (has_prev) {
            const float4 p0 = prev[(size_t)v * pvs4 + (size_t)f * pfs4 + t];
            const float4 p1 = prev[(size_t)v * pvs4 + (size_t)(f + 1) * pfs4 + t];
            a0.x = 2.f * a0.x - p0.x; a0.y = 2.f * a0.y - p0.y;
            a0.z = 2.f * a0.z - p0.z; a0.w = 2.f * a0.w - p0.w;
            a1.x = 2.f * a1.x - p1.x; a1.y = 2.f * a1.y - p1.y;
            a1.z = 2.f * a1.z - p1.z; a1.w = 2.f * a1.w - p1.w;
        }
        next[(size_t)v * DD4 + f * SP4 + t]       = a0;
        next[(size_t)v * DD4 + (f + 1) * SP4 + t] = a1;
    }
}

// Final (R3 structure, f32x2 math, 3 blocks/SM): one block per vertex,
// 256 threads. Phase 1: cooperative x4 gather into 16 KB smem. Phase 2:
// two o-groups x 128 spatial threads, 8 outputs each, packed FFMA2.
__global__ __launch_bounds__(2 * SP4, 3) void final_kernel(
    const float4* __restrict__ x0,
    const float4* __restrict__ x1,
    const float4* __restrict__ x2,
    const float4* __restrict__ x3,
    const int* __restrict__ cols, const float* __restrict__ vals,
    const float* __restrict__ weight, const float* __restrict__ bias,
    float4* __restrict__ out)
{
    __shared__ int    scol[DEG];
    __shared__ float2 sval2[DEG];                // duplicated laplacian weights
    __shared__ float2 sw2[KCH * FIN * FOUT];     // duplicated einsum weights (5 KB)
    __shared__ float2 sb2[FOUT];
    __shared__ float4 sx4[FIN * SP4];            // 16 KB: x4 row for this vertex

    const int v   = blockIdx.x;
    const int tid = threadIdx.x;

    if (tid < DEG) {
        scol[tid] = cols[v * DEG + tid];
        const float w = vals[v * DEG + tid];
        sval2[tid] = make_float2(w, w);
    }
    for (int i = tid; i < KCH * FIN * FOUT; i += 2 * SP4) {
        const float w = weight[i];
        sw2[i] = make_float2(w, w);
    }
    if (tid < FOUT) {
        const float b = bias[tid];
        sb2[tid] = make_float2(b, b);
    }
    __syncthreads();

    // Phase 1: 256 threads compute x4[v, f, t] = 2*spmv(x3) - x2 into smem.
    #pragma unroll 1
    for (int j = 0; j < (FIN * SP4) / (2 * SP4); ++j) {   // 4 iterations
        const int idx = tid + j * (2 * SP4);
        const int f   = idx >> 7;          // /128
        const int t   = idx & (SP4 - 1);

        ull axy = 0, azw = 0;
        #pragma unroll
        for (int n = 0; n < DEG; ++n) {
            const ulonglong2 x = ((const ulonglong2*)x3)[(size_t)scol[n] * DD4 + f * SP4 + t];
            const ull w2 = *(const ull*)&sval2[n];
            FMA2(axy, x.x, w2, axy);
            FMA2(azw, x.y, w2, azw);
        }
        const ulonglong2 p2 = ((const ulonglong2*)x2)[(size_t)v * DD4 + f * SP4 + t];
        // x4 = 2*acc - p2  (negate p2 lanes by sign-bit xor, then packed fma)
        const ull np2x = p2.x ^ SIGNMASK2;
        const ull np2y = p2.y ^ SIGNMASK2;
        ull rxy, rzw;
        FMA2(rxy, axy, (ull)TWO2, np2x);
        FMA2(rzw, azw, (ull)TWO2, np2y);
        ulonglong2 r; r.x = rxy; r.y = rzw;
        ((ulonglong2*)sx4)[idx] = r;
    }
    __syncthreads();

    // Phase 2: o-group split. Threads [0,128) -> o=0..7, [128,256) -> o=8..15.
    const int half   = tid >> 7;           // 0 or 1
    const int o_base = half * (FOUT / 2);
    const int t      = tid & (SP4 - 1);

    ull cxy[FOUT / 2], czw[FOUT / 2];
    #pragma unroll
    for (int oo = 0; oo < FOUT / 2; ++oo) {
        const ull b2 = *(const ull*)&sb2[o_base + oo];
        cxy[oo] = b2;
        czw[oo] = b2;
    }

    #pragma unroll 1
    for (int f = 0; f < FIN; ++f) {
        const ulonglong2 x0v = ((const ulonglong2*)x0)[(size_t)f * (NV * SP4) + (size_t)v * SP4 + t];
        const ulonglong2 x1v = ((const ulonglong2*)x1)[(size_t)v * DD4 + f * SP4 + t];
        const ulonglong2 x2v = ((const ulonglong2*)x2)[(size_t)v * DD4 + f * SP4 + t];
        const ulonglong2 x3v = ((const ulonglong2*)x3)[(size_t)v * DD4 + f * SP4 + t];
        const ulonglong2 x4v = ((const ulonglong2*)sx4)[f * SP4 + t];

        #pragma unroll
        for (int oo = 0; oo < FOUT / 2; ++oo) {
            const int o = o_base + oo;
            const ull w0 = *(const ull*)&sw2[0 * FIN * FOUT + f * FOUT + o];
            const ull w1 = *(const ull*)&sw2[1 * FIN * FOUT + f * FOUT + o];
            const ull w2 = *(const ull*)&sw2[2 * FIN * FOUT + f * FOUT + o];
            const ull w3 = *(const ull*)&sw2[3 * FIN * FOUT + f * FOUT + o];
            const ull w4 = *(const ull*)&sw2[4 * FIN * FOUT + f * FOUT + o];
            FMA2(cxy[oo], x0v.x, w0, cxy[oo]);  FMA2(czw[oo], x0v.y, w0, czw[oo]);
            FMA2(cxy[oo], x1v.x, w1, cxy[oo]);  FMA2(czw[oo], x1v.y, w1, czw[oo]);
            FMA2(cxy[oo], x2v.x, w2, cxy[oo]);  FMA2(czw[oo], x2v.y, w2, czw[oo]);
            FMA2(cxy[oo], x3v.x, w3, cxy[oo]);  FMA2(czw[oo], x3v.y, w3, czw[oo]);
            FMA2(cxy[oo], x4v.x, w4, cxy[oo]);  FMA2(czw[oo], x4v.y, w4, czw[oo]);
        }
    }

    #pragma unroll
    for (int oo = 0; oo < FOUT / 2; ++oo) {
        float4 r;
        *(ull*)&r.x = cxy[oo];      // lanes (x, y)
        *(ull*)&r.z = czw[oo];      // lanes (z, w)
        __stcs(&out[(size_t)(o_base + oo) * (NV * SP4) + (size_t)v * SP4 + t], r);
    }
}

extern "C" void kernel_launch(void* const* d_in, const int* in_sizes, int n_in,
                              void* d_out, int out_size) {
    const float* inputs = (const float*)d_in[0];
    // d_in[1] = lap_rows (unused: rows are repeat(arange(V), DEG) by construction)
    const int*   cols   = (const int*)d_in[2];
    const float* vals   = (const float*)d_in[3];
    const float* weight = (const float*)d_in[4];
    const float* bias   = (const float*)d_in[5];
    float4*      out    = (float4*)d_out;

    void* sym = nullptr;
    cudaGetSymbolAddress(&sym, g_buf);
    float4* g0 = (float4*)sym;
    float4* g1 = g0 + (size_t)NV * DD4;
    float4* g2 = g1 + (size_t)NV * DD4;

    const float4* in4 = (const float4*)inputs;
    const int IVS4 = SP4;            // input vertex stride (float4)
    const int IFS4 = NV * SP4;       // input feature stride (float4)

    // x1 = L @ x0 (x0 read directly from inputs layout)
    spmv_step_kernel<<<NV, SP4>>>(in4, IVS4, IFS4, nullptr, 0, 0,
                                  g0, cols, vals, 0);
    // x2 = 2 L x1 - x0
    spmv_step_kernel<<<NV, SP4>>>(g0, DD4, SP4, in4, IVS4, IFS4,
                                  g1, cols, vals, 1);
    // x3 = 2 L x2 - x1
    spmv_step_kernel<<<NV, SP4>>>(g1, DD4, SP4, g0, DD4, SP4,
                                  g2, cols, vals, 1);
    // x4 (smem) + einsum over (k,f) + bias -> out, packed f32x2 math
    final_kernel<<<NV, 2 * SP4>>>(in4, g0, g1, g2, cols, vals, weight, bias, out);
}

// round 9
// speedup vs baseline: 1.0026x; 1.0026x over previous
#include <cuda_runtime.h>

#define NV   2562
#define DEG  8
#define FIN  8
#define FOUT 16
#define KCH  5
#define SP   512                 // spatial = X*Y*Z
#define SP4  (SP/4)              // 128 float4 per (v,f) row-chunk
#define DD   (FIN*SP)            // 4096 floats per vertex row
#define DD4  (DD/4)              // 1024 float4

// Scratch: 4 Chebyshev levels (x1, x2, x3, x4), 42 MB each.
__device__ float4 g_buf[4][(size_t)NV * DD4];

// One block per vertex v; 128 threads cover the 512 spatial floats as float4.
// Two f-iterations interleaved -> 16 independent gather loads in flight.
__global__ __launch_bounds__(SP4) void spmv_step_kernel(
    const float4* __restrict__ cur,  int cvs4, int cfs4,   // strides in float4 units
    const float4* __restrict__ prev, int pvs4, int pfs4,
    float4* __restrict__ next,
    const int* __restrict__ cols, const float* __restrict__ vals,
    int has_prev)
{
    __shared__ int   scol[DEG];
    __shared__ float sval[DEG];
    const int v = blockIdx.x;
    const int t = threadIdx.x;
    if (t < DEG) {
        scol[t] = cols[v * DEG + t];
        sval[t] = vals[v * DEG + t];
    }
    __syncthreads();

    #pragma unroll
    for (int f = 0; f < FIN; f += 2) {
        float4 a0 = make_float4(0.f, 0.f, 0.f, 0.f);
        float4 a1 = make_float4(0.f, 0.f, 0.f, 0.f);
        #pragma unroll
        for (int n = 0; n < DEG; ++n) {
            const size_t base = (size_t)scol[n] * cvs4 + (size_t)f * cfs4 + t;
            const float4 x0 = cur[base];
            const float4 x1 = cur[base + cfs4];
            const float  w  = sval[n];
            a0.x += w * x0.x; a0.y += w * x0.y; a0.z += w * x0.z; a0.w += w * x0.w;
            a1.x += w * x1.x; a1.y += w * x1.y; a1.z += w * x1.z; a1.w += w * x1.w;
        }
        if (has_prev) {
            const float4 p0 = prev[(size_t)v * pvs4 + (size_t)f * pfs4 + t];
            const float4 p1 = prev[(size_t)v * pvs4 + (size_t)(f + 1) * pfs4 + t];
            a0.x = 2.f * a0.x - p0.x; a0.y = 2.f * a0.y - p0.y;
            a0.z = 2.f * a0.z - p0.z; a0.w = 2.f * a0.w - p0.w;
            a1.x = 2.f * a1.x - p1.x; a1.y = 2.f * a1.y - p1.y;
            a1.z = 2.f * a1.z - p1.z; a1.w = 2.f * a1.w - p1.w;
        }
        next[(size_t)v * DD4 + f * SP4 + t]       = a0;
        next[(size_t)v * DD4 + (f + 1) * SP4 + t] = a1;
    }
}

// Pure streaming einsum: out[o,v,s] = bias[o] + sum_{k,f} w[k,f,o] * xk[f,v,s].
// One block per vertex, 256 threads = 2 o-halves x 128 spatial float4.
// No gathers, no phases; 3 blocks/SM via reg cap.
__global__ __launch_bounds__(2 * SP4, 3) void einsum_kernel(
    const float4* __restrict__ x0,
    const float4* __restrict__ x1,
    const float4* __restrict__ x2,
    const float4* __restrict__ x3,
    const float4* __restrict__ x4,
    const float* __restrict__ weight, const float* __restrict__ bias,
    float4* __restrict__ out)
{
    __shared__ float sw[KCH * FIN * FOUT];   // 640 floats, [k][f][o]
    __shared__ float sb[FOUT];

    const int v   = blockIdx.x;
    const int tid = threadIdx.x;

    for (int i = tid; i < KCH * FIN * FOUT; i += 2 * SP4) sw[i] = weight[i];
    if (tid < FOUT) sb[tid] = bias[tid];
    __syncthreads();

    const int half   = tid >> 7;           // 0 or 1
    const int o_base = half * (FOUT / 2);
    const int t      = tid & (SP4 - 1);

    float4 c[FOUT / 2];
    #pragma unroll
    for (int oo = 0; oo < FOUT / 2; ++oo) {
        const float b = sb[o_base + oo];
        c[oo] = make_float4(b, b, b, b);
    }

    #pragma unroll
    for (int f = 0; f < FIN; ++f) {
        const float4 x0f = x0[(size_t)f * (NV * SP4) + (size_t)v * SP4 + t];
        const float4 x1f = x1[(size_t)v * DD4 + f * SP4 + t];
        const float4 x2f = x2[(size_t)v * DD4 + f * SP4 + t];
        const float4 x3f = x3[(size_t)v * DD4 + f * SP4 + t];
        const float4 x4f = x4[(size_t)v * DD4 + f * SP4 + t];

        #pragma unroll
        for (int oo = 0; oo < FOUT / 2; ++oo) {
            const int o = o_base + oo;
            const float w0 = sw[0 * FIN * FOUT + f * FOUT + o];
            const float w1 = sw[1 * FIN * FOUT + f * FOUT + o];
            const float w2 = sw[2 * FIN * FOUT + f * FOUT + o];
            const float w3 = sw[3 * FIN * FOUT + f * FOUT + o];
            const float w4 = sw[4 * FIN * FOUT + f * FOUT + o];
            c[oo].x += x0f.x*w0 + x1f.x*w1 + x2f.x*w2 + x3f.x*w3 + x4f.x*w4;
            c[oo].y += x0f.y*w0 + x1f.y*w1 + x2f.y*w2 + x3f.y*w3 + x4f.y*w4;
            c[oo].z += x0f.z*w0 + x1f.z*w1 + x2f.z*w2 + x3f.z*w3 + x4f.z*w4;
            c[oo].w += x0f.w*w0 + x1f.w*w1 + x2f.w*w2 + x3f.w*w3 + x4f.w*w4;
        }
    }

    #pragma unroll
    for (int oo = 0; oo < FOUT / 2; ++oo)
        __stcs(&out[(size_t)(o_base + oo) * (NV * SP4) + (size_t)v * SP4 + t], c[oo]);
}

extern "C" void kernel_launch(void* const* d_in, const int* in_sizes, int n_in,
                              void* d_out, int out_size) {
    const float* inputs = (const float*)d_in[0];
    // d_in[1] = lap_rows (unused: rows are repeat(arange(V), DEG) by construction)
    const int*   cols   = (const int*)d_in[2];
    const float* vals   = (const float*)d_in[3];
    const float* weight = (const float*)d_in[4];
    const float* bias   = (const float*)d_in[5];
    float4*      out    = (float4*)d_out;

    void* sym = nullptr;
    cudaGetSymbolAddress(&sym, g_buf);
    float4* g0 = (float4*)sym;                       // x1
    float4* g1 = g0 + (size_t)NV * DD4;              // x2
    float4* g2 = g1 + (size_t)NV * DD4;              // x3
    float4* g3 = g2 + (size_t)NV * DD4;              // x4

    const float4* in4 = (const float4*)inputs;
    const int IVS4 = SP4;            // input vertex stride (float4)
    const int IFS4 = NV * SP4;       // input feature stride (float4)

    // x1 = L @ x0 (x0 read directly from inputs layout)
    spmv_step_kernel<<<NV, SP4>>>(in4, IVS4, IFS4, nullptr, 0, 0,
                                  g0, cols, vals, 0);
    // x2 = 2 L x1 - x0
    spmv_step_kernel<<<NV, SP4>>>(g0, DD4, SP4, in4, IVS4, IFS4,
                                  g1, cols, vals, 1);
    // x3 = 2 L x2 - x1
    spmv_step_kernel<<<NV, SP4>>>(g1, DD4, SP4, g0, DD4, SP4,
                                  g2, cols, vals, 1);
    // x4 = 2 L x3 - x2
    spmv_step_kernel<<<NV, SP4>>>(g2, DD4, SP4, g1, DD4, SP4,
                                  g3, cols, vals, 1);
    // Pure streaming einsum over (k,f) + bias -> out
    einsum_kernel<<<NV, 2 * SP4>>>(in4, g0, g1, g2, g3, weight, bias, out);
}

// round 10
// speedup vs baseline: 1.1308x; 1.1279x over previous
#include <cuda_runtime.h>

#define NV   2562
#define DEG  8
#define FIN  8
#define FOUT 16
#define KCH  5
#define SP   512                 // spatial = X*Y*Z
#define SP4  (SP/4)              // 128 float4 per (v,f) row-chunk
#define DD   (FIN*SP)            // 4096 floats per vertex row
#define DD4  (DD/4)              // 1024 float4

// Scratch: 3 rolling Chebyshev levels (x1, x2, x3), 42 MB each.
__device__ float4 g_buf[3][(size_t)NV * DD4];

// One block per vertex v; 128 threads cover the 512 spatial floats as float4.
// Two f-iterations interleaved -> 16 independent gather loads in flight.
__global__ __launch_bounds__(SP4) void spmv_step_kernel(
    const float4* __restrict__ cur,  int cvs4, int cfs4,   // strides in float4 units
    const float4* __restrict__ prev, int pvs4, int pfs4,
    float4* __restrict__ next,
    const int* __restrict__ cols, const float* __restrict__ vals,
    int has_prev)
{
    __shared__ int   scol[DEG];
    __shared__ float sval[DEG];
    const int v = blockIdx.x;
    const int t = threadIdx.x;
    if (t < DEG) {
        scol[t] = cols[v * DEG + t];
        sval[t] = vals[v * DEG + t];
    }
    __syncthreads();

    #pragma unroll
    for (int f = 0; f < FIN; f += 2) {
        float4 a0 = make_float4(0.f, 0.f, 0.f, 0.f);
        float4 a1 = make_float4(0.f, 0.f, 0.f, 0.f);
        #pragma unroll
        for (int n = 0; n < DEG; ++n) {
            const size_t base = (size_t)scol[n] * cvs4 + (size_t)f * cfs4 + t;
            const float4 x0 = cur[base];
            const float4 x1 = cur[base + cfs4];
            const float  w  = sval[n];
            a0.x += w * x0.x; a0.y += w * x0.y; a0.z += w * x0.z; a0.w += w * x0.w;
            a1.x += w * x1.x; a1.y += w * x1.y; a1.z += w * x1.z; a1.w += w * x1.w;
        }
        if (has_prev) {
            const float4 p0 = prev[(size_t)v * pvs4 + (size_t)f * pfs4 + t];
            const float4 p1 = prev[(size_t)v * pvs4 + (size_t)(f + 1) * pfs4 + t];
            a0.x = 2.f * a0.x - p0.x; a0.y = 2.f * a0.y - p0.y;
            a0.z = 2.f * a0.z - p0.z; a0.w = 2.f * a0.w - p0.w;
            a1.x = 2.f * a1.x - p1.x; a1.y = 2.f * a1.y - p1.y;
            a1.z = 2.f * a1.z - p1.z; a1.w = 2.f * a1.w - p1.w;
        }
        next[(size_t)v * DD4 + f * SP4 + t]       = a0;
        next[(size_t)v * DD4 + (f + 1) * SP4 + t] = a1;
    }
}

// Final (R3 structure + reg cap + vectorized weight LDS): one block per
// vertex, 256 threads. Phase 1: cooperative x4 gather into 16 KB smem.
// Phase 2: two o-halves x 128 spatial threads, 8 outputs each; weights
// consumed per-k as float4 broadcasts (LDS.128), minimizing issue slots
// and register liveness.
__global__ __launch_bounds__(2 * SP4, 3) void final_kernel(
    const float4* __restrict__ x0,
    const float4* __restrict__ x1,
    const float4* __restrict__ x2,
    const float4* __restrict__ x3,
    const int* __restrict__ cols, const float* __restrict__ vals,
    const float* __restrict__ weight, const float* __restrict__ bias,
    float4* __restrict__ out)
{
    __shared__ int    scol[DEG];
    __shared__ float  sval[DEG];
    __shared__ float4 sw4[KCH * FIN * (FOUT / 4)];   // weights as o-quads
    __shared__ float  sb[FOUT];
    __shared__ float4 sx4[FIN * SP4];                // 16 KB: x4 row

    const int v   = blockIdx.x;
    const int tid = threadIdx.x;

    if (tid < DEG) {
        scol[tid] = cols[v * DEG + tid];
        sval[tid] = vals[v * DEG + tid];
    }
    // weight is [k][f][o] with o contiguous -> o-quads are natural float4s
    for (int i = tid; i < KCH * FIN * (FOUT / 4); i += 2 * SP4)
        sw4[i] = ((const float4*)weight)[i];
    if (tid < FOUT) sb[tid] = bias[tid];
    __syncthreads();

    // Phase 1: 256 threads compute x4[v, f, t] = 2*spmv(x3) - x2 into smem.
    #pragma unroll 1
    for (int j = 0; j < (FIN * SP4) / (2 * SP4); ++j) {   // 4 iterations
        const int idx = tid + j * (2 * SP4);
        const int f   = idx >> 7;          // /128
        const int t   = idx & (SP4 - 1);
        float4 acc = make_float4(0.f, 0.f, 0.f, 0.f);
        #pragma unroll
        for (int n = 0; n < DEG; ++n) {
            const float4 x = x3[(size_t)scol[n] * DD4 + f * SP4 + t];
            const float  w = sval[n];
            acc.x += w * x.x; acc.y += w * x.y;
            acc.z += w * x.z; acc.w += w * x.w;
        }
        const float4 p2 = x2[(size_t)v * DD4 + f * SP4 + t];
        acc.x = 2.f * acc.x - p2.x; acc.y = 2.f * acc.y - p2.y;
        acc.z = 2.f * acc.z - p2.z; acc.w = 2.f * acc.w - p2.w;
        sx4[idx] = acc;
    }
    __syncthreads();

    // Phase 2: o-half split. Threads [0,128) -> o=0..7, [128,256) -> o=8..15.
    const int half   = tid >> 7;           // 0 or 1
    const int o_base = half * (FOUT / 2);
    const int t      = tid & (SP4 - 1);

    float4 c[FOUT / 2];
    #pragma unroll
    for (int oo = 0; oo < FOUT / 2; ++oo) {
        const float b = sb[o_base + oo];
        c[oo] = make_float4(b, b, b, b);
    }

    #pragma unroll 1
    for (int f = 0; f < FIN; ++f) {
        float4 xk[KCH];
        xk[0] = x0[(size_t)f * (NV * SP4) + (size_t)v * SP4 + t];
        xk[1] = x1[(size_t)v * DD4 + f * SP4 + t];
        xk[2] = x2[(size_t)v * DD4 + f * SP4 + t];
        xk[3] = x3[(size_t)v * DD4 + f * SP4 + t];
        xk[4] = sx4[f * SP4 + t];

        #pragma unroll
        for (int k = 0; k < KCH; ++k) {
            // two o-quads for this (k, f, half): 8 weight scalars via 2 LDS.128
            const float4 wa = sw4[(k * FIN + f) * (FOUT / 4) + half * 2];
            const float4 wb = sw4[(k * FIN + f) * (FOUT / 4) + half * 2 + 1];
            const float4 xv = xk[k];

            c[0].x += xv.x * wa.x; c[0].y += xv.y * wa.x; c[0].z += xv.z * wa.x; c[0].w += xv.w * wa.x;
            c[1].x += xv.x * wa.y; c[1].y += xv.y * wa.y; c[1].z += xv.z * wa.y; c[1].w += xv.w * wa.y;
            c[2].x += xv.x * wa.z; c[2].y += xv.y * wa.z; c[2].z += xv.z * wa.z; c[2].w += xv.w * wa.z;
            c[3].x += xv.x * wa.w; c[3].y += xv.y * wa.w; c[3].z += xv.z * wa.w; c[3].w += xv.w * wa.w;
            c[4].x += xv.x * wb.x; c[4].y += xv.y * wb.x; c[4].z += xv.z * wb.x; c[4].w += xv.w * wb.x;
            c[5].x += xv.x * wb.y; c[5].y += xv.y * wb.y; c[5].z += xv.z * wb.y; c[5].w += xv.w * wb.y;
            c[6].x += xv.x * wb.z; c[6].y += xv.y * wb.z; c[6].z += xv.z * wb.z; c[6].w += xv.w * wb.z;
            c[7].x += xv.x * wb.w; c[7].y += xv.y * wb.w; c[7].z += xv.z * wb.w; c[7].w += xv.w * wb.w;
        }
    }

    #pragma unroll
    for (int oo = 0; oo < FOUT / 2; ++oo)
        __stcs(&out[(size_t)(o_base + oo) * (NV * SP4) + (size_t)v * SP4 + t], c[oo]);
}

extern "C" void kernel_launch(void* const* d_in, const int* in_sizes, int n_in,
                              void* d_out, int out_size) {
    const float* inputs = (const float*)d_in[0];
    // d_in[1] = lap_rows (unused: rows are repeat(arange(V), DEG) by construction)
    const int*   cols   = (const int*)d_in[2];
    const float* vals   = (const float*)d_in[3];
    const float* weight = (const float*)d_in[4];
    const float* bias   = (const float*)d_in[5];
    float4*      out    = (float4*)d_out;

    void* sym = nullptr;
    cudaGetSymbolAddress(&sym, g_buf);
    float4* g0 = (float4*)sym;
    float4* g1 = g0 + (size_t)NV * DD4;
    float4* g2 = g1 + (size_t)NV * DD4;

    const float4* in4 = (const float4*)inputs;
    const int IVS4 = SP4;            // input vertex stride (float4)
    const int IFS4 = NV * SP4;       // input feature stride (float4)

    // x1 = L @ x0 (x0 read directly from inputs layout)
    spmv_step_kernel<<<NV, SP4>>>(in4, IVS4, IFS4, nullptr, 0, 0,
                                  g0, cols, vals, 0);
    // x2 = 2 L x1 - x0
    spmv_step_kernel<<<NV, SP4>>>(g0, DD4, SP4, in4, IVS4, IFS4,
                                  g1, cols, vals, 1);
    // x3 = 2 L x2 - x1
    spmv_step_kernel<<<NV, SP4>>>(g1, DD4, SP4, g0, DD4, SP4,
                                  g2, cols, vals, 1);
    // x4 (smem) + einsum over (k,f) + bias -> out
    final_kernel<<<NV, 2 * SP4>>>(in4, g0, g1, g2, cols, vals, weight, bias, out);
}

// round 11
// speedup vs baseline: 1.2024x; 1.0634x over previous
#include <cuda_runtime.h>

#define NV   2562
#define DEG  8
#define FIN  8
#define FOUT 16
#define KCH  5
#define SP   512                 // spatial = X*Y*Z
#define SP4  (SP/4)              // 128 float4 per (v,f) row
#define HS4  (SP4/2)             // 64 float4 per (v,f) half-slice
#define DD   (FIN*SP)            // 4096 floats per vertex row
#define DD4  (DD/4)              // 1024 float4

// Scratch: 3 rolling Chebyshev levels (x1, x2, x3), 42 MB each, [v,f,s] layout.
__device__ float4 g_buf[3][(size_t)NV * DD4];

// SpMV on a spatial half-slice. One block per vertex; 128 threads =
// 2 f-groups x 64 spatial float4. Each f-group covers 4 f's, 2-way interleaved.
__global__ __launch_bounds__(128) void spmv_slice_kernel(
    const float4* __restrict__ cur,  int cvs4, int cfs4,   // strides in float4
    const float4* __restrict__ prev, int pvs4, int pfs4,
    float4* __restrict__ next,
    const int* __restrict__ cols, const float* __restrict__ vals,
    int has_prev, int s0)
{
    __shared__ int   scol[DEG];
    __shared__ float sval[DEG];
    const int v   = blockIdx.x;
    const int tid = threadIdx.x;
    const int t   = (tid & (HS4 - 1)) + s0;     // spatial float4 index
    const int fg  = tid >> 6;                    // 0 or 1
    if (tid < DEG) {
        scol[tid] = cols[v * DEG + tid];
        sval[tid] = vals[v * DEG + tid];
    }
    __syncthreads();

    #pragma unroll
    for (int fi = 0; fi < 4; fi += 2) {
        const int f = fg * 4 + fi;
        float4 a0 = make_float4(0.f, 0.f, 0.f, 0.f);
        float4 a1 = make_float4(0.f, 0.f, 0.f, 0.f);
        #pragma unroll
        for (int n = 0; n < DEG; ++n) {
            const size_t base = (size_t)scol[n] * cvs4 + (size_t)f * cfs4 + t;
            const float4 x0 = cur[base];
            const float4 x1 = cur[base + cfs4];
            const float  w  = sval[n];
            a0.x += w * x0.x; a0.y += w * x0.y; a0.z += w * x0.z; a0.w += w * x0.w;
            a1.x += w * x1.x; a1.y += w * x1.y; a1.z += w * x1.z; a1.w += w * x1.w;
        }
        if (has_prev) {
            const float4 p0 = prev[(size_t)v * pvs4 + (size_t)f * pfs4 + t];
            const float4 p1 = prev[(size_t)v * pvs4 + (size_t)(f + 1) * pfs4 + t];
            a0.x = 2.f * a0.x - p0.x; a0.y = 2.f * a0.y - p0.y;
            a0.z = 2.f * a0.z - p0.z; a0.w = 2.f * a0.w - p0.w;
            a1.x = 2.f * a1.x - p1.x; a1.y = 2.f * a1.y - p1.y;
            a1.z = 2.f * a1.z - p1.z; a1.w = 2.f * a1.w - p1.w;
        }
        next[(size_t)v * DD4 + f * SP4 + t]       = a0;
        next[(size_t)v * DD4 + (f + 1) * SP4 + t] = a1;
    }
}

// Final on a half-slice: phase 1 computes x4 slice into smem; phase 2 does
// the (k,f)->o contraction with vectorized weight broadcasts (R10 scheme).
// 128 threads = 2 o-halves x 64 spatial float4.
__global__ __launch_bounds__(128, 6) void final_slice_kernel(
    const float4* __restrict__ x0,
    const float4* __restrict__ x1,
    const float4* __restrict__ x2,
    const float4* __restrict__ x3,
    const int* __restrict__ cols, const float* __restrict__ vals,
    const float* __restrict__ weight, const float* __restrict__ bias,
    float4* __restrict__ out, int s0)
{
    __shared__ int    scol[DEG];
    __shared__ float  sval[DEG];
    __shared__ float4 sw4[KCH * FIN * (FOUT / 4)];   // weights as o-quads
    __shared__ float  sb[FOUT];
    __shared__ float4 sx4[FIN * HS4];                // 8 KB: x4 half-row

    const int v   = blockIdx.x;
    const int tid = threadIdx.x;

    if (tid < DEG) {
        scol[tid] = cols[v * DEG + tid];
        sval[tid] = vals[v * DEG + tid];
    }
    for (int i = tid; i < KCH * FIN * (FOUT / 4); i += 128)
        sw4[i] = ((const float4*)weight)[i];
    if (tid < FOUT) sb[tid] = bias[tid];
    __syncthreads();

    // Phase 1: x4[v, f, s0+t] = 2*spmv(x3) - x2 into smem.
    #pragma unroll 1
    for (int j = 0; j < (FIN * HS4) / 128; ++j) {     // 4 iterations
        const int idx = tid + j * 128;
        const int f   = idx >> 6;                     // /64
        const int t   = (idx & (HS4 - 1)) + s0;
        float4 acc = make_float4(0.f, 0.f, 0.f, 0.f);
        #pragma unroll
        for (int n = 0; n < DEG; ++n) {
            const float4 x = x3[(size_t)scol[n] * DD4 + f * SP4 + t];
            const float  w = sval[n];
            acc.x += w * x.x; acc.y += w * x.y;
            acc.z += w * x.z; acc.w += w * x.w;
        }
        const float4 p2 = x2[(size_t)v * DD4 + f * SP4 + t];
        acc.x = 2.f * acc.x - p2.x; acc.y = 2.f * acc.y - p2.y;
        acc.z = 2.f * acc.z - p2.z; acc.w = 2.f * acc.w - p2.w;
        sx4[idx] = acc;
    }
    __syncthreads();

    // Phase 2: o-half split.
    const int half   = tid >> 6;                 // 0 or 1
    const int o_base = half * (FOUT / 2);
    const int ts     = tid & (HS4 - 1);          // slice-local spatial
    const int t      = ts + s0;                  // global spatial float4

    float4 c[FOUT / 2];
    #pragma unroll
    for (int oo = 0; oo < FOUT / 2; ++oo) {
        const float b = sb[o_base + oo];
        c[oo] = make_float4(b, b, b, b);
    }

    #pragma unroll 1
    for (int f = 0; f < FIN; ++f) {
        float4 xk[KCH];
        xk[0] = x0[(size_t)f * (NV * SP4) + (size_t)v * SP4 + t];
        xk[1] = x1[(size_t)v * DD4 + f * SP4 + t];
        xk[2] = x2[(size_t)v * DD4 + f * SP4 + t];
        xk[3] = x3[(size_t)v * DD4 + f * SP4 + t];
        xk[4] = sx4[f * HS4 + ts];

        #pragma unroll
        for (int k = 0; k < KCH; ++k) {
            const float4 wa = sw4[(k * FIN + f) * (FOUT / 4) + half * 2];
            const float4 wb = sw4[(k * FIN + f) * (FOUT / 4) + half * 2 + 1];
            const float4 xv = xk[k];
            c[0].x += xv.x * wa.x; c[0].y += xv.y * wa.x; c[0].z += xv.z * wa.x; c[0].w += xv.w * wa.x;
            c[1].x += xv.x * wa.y; c[1].y += xv.y * wa.y; c[1].z += xv.z * wa.y; c[1].w += xv.w * wa.y;
            c[2].x += xv.x * wa.z; c[2].y += xv.y * wa.z; c[2].z += xv.z * wa.z; c[2].w += xv.w * wa.z;
            c[3].x += xv.x * wa.w; c[3].y += xv.y * wa.w; c[3].z += xv.z * wa.w; c[3].w += xv.w * wa.w;
            c[4].x += xv.x * wb.x; c[4].y += xv.y * wb.x; c[4].z += xv.z * wb.x; c[4].w += xv.w * wb.x;
            c[5].x += xv.x * wb.y; c[5].y += xv.y * wb.y; c[5].z += xv.z * wb.y; c[5].w += xv.w * wb.y;
            c[6].x += xv.x * wb.z; c[6].y += xv.y * wb.z; c[6].z += xv.z * wb.z; c[6].w += xv.w * wb.z;
            c[7].x += xv.x * wb.w; c[7].y += xv.y * wb.w; c[7].z += xv.z * wb.w; c[7].w += xv.w * wb.w;
        }
    }

    #pragma unroll
    for (int oo = 0; oo < FOUT / 2; ++oo)
        __stcs(&out[(size_t)(o_base + oo) * (NV * SP4) + (size_t)v * SP4 + t], c[oo]);
}

extern "C" void kernel_launch(void* const* d_in, const int* in_sizes, int n_in,
                              void* d_out, int out_size) {
    const float* inputs = (const float*)d_in[0];
    // d_in[1] = lap_rows (unused: rows are repeat(arange(V), DEG) by construction)
    const int*   cols   = (const int*)d_in[2];
    const float* vals   = (const float*)d_in[3];
    const float* weight = (const float*)d_in[4];
    const float* bias   = (const float*)d_in[5];
    float4*      out    = (float4*)d_out;

    void* sym = nullptr;
    cudaGetSymbolAddress(&sym, g_buf);
    float4* g0 = (float4*)sym;
    float4* g1 = g0 + (size_t)NV * DD4;
    float4* g2 = g1 + (size_t)NV * DD4;

    const float4* in4 = (const float4*)inputs;
    const int IVS4 = SP4;            // input vertex stride (float4)
    const int IFS4 = NV * SP4;       // input feature stride (float4)

    // Two spatial half-slice passes; per-pass working set (~84 MB) is
    // L2-resident across the 4 launches (L2 persists across launches).
    for (int s = 0; s < 2; ++s) {
        const int s0 = s * HS4;
        // x1 = L @ x0
        spmv_slice_kernel<<<NV, 128>>>(in4, IVS4, IFS4, nullptr, 0, 0,
                                       g0, cols, vals, 0, s0);
        // x2 = 2 L x1 - x0
        spmv_slice_kernel<<<NV, 128>>>(g0, DD4, SP4, in4, IVS4, IFS4,
                                       g1, cols, vals, 1, s0);
        // x3 = 2 L x2 - x1
        spmv_slice_kernel<<<NV, 128>>>(g1, DD4, SP4, g0, DD4, SP4,
                                       g2, cols, vals, 1, s0);
        // x4 (smem) + einsum + bias -> out
        final_slice_kernel<<<NV, 128>>>(in4, g0, g1, g2, cols, vals,
                                        weight, bias, out, s0);
    }
}